// round 7
// baseline (speedup 1.0000x reference)
#include <cuda_runtime.h>
#include <cuda.h>
#include <cuda_fp16.h>
#include <cuda_fp8.h>
#include <cstdint>

#define DI __device__ __forceinline__

// ---------------- problem dims ----------------
static constexpr int M_DIM = 8192;
static constexpr int N_DIM = 4096;
static constexpr int K_DIM = 4096;

// ---------------- GEMM tiling ----------------
static constexpr int TILE_M = 128;
static constexpr int TILE_N = 256;
static constexpr int KCHUNK = 64;                      // fp16 elems per k-chunk (128B rows, SW128)
static constexpr int NCHUNKS = K_DIM / KCHUNK;         // 64
static constexpr int STAGES  = 4;
static constexpr int NTILES  = (M_DIM / TILE_M) * (N_DIM / TILE_N);  // 1024
static constexpr int GRID_SM = 148;                    // persistent CTAs (1/SM)
static constexpr int A_BYTES = TILE_M * KCHUNK * 2;    // 16 KB
static constexpr int B_BYTES = TILE_N * KCHUNK * 2;    // 32 KB
static constexpr int STAGE_BYTES = A_BYTES + B_BYTES;  // 48 KB
static constexpr int SMEM_CTRL  = 1024;
static constexpr int SMEM_REQ   = SMEM_CTRL + STAGES * STAGE_BYTES + 1024;  // ~199 KB

#define OFF_FULL(s)  ((s)*16)
#define OFF_EMPTY(s) ((s)*16 + 8)

// ---------------- device scratch (no cudaMalloc allowed) ----------------
__device__ __align__(1024) __half g_wdq[(size_t)N_DIM * K_DIM];   // 32 MB
__device__ __align__(1024) __half g_xh[(size_t)M_DIM * K_DIM];    // 64 MB

// ---------------- PTX helpers ----------------
DI uint32_t smem_u32(const void* p) {
    uint32_t a;
    asm("{ .reg .u64 t; cvta.to.shared.u64 t, %1; cvt.u32.u64 %0, t; }" : "=r"(a) : "l"(p));
    return a;
}

#define MBAR_INIT(mbar, cnt) \
    asm volatile("mbarrier.init.shared.b64 [%0], %1;" :: "r"((uint32_t)(mbar)), "r"((uint32_t)(cnt)) : "memory")
#define MBAR_EXPECT_TX(mbar, bytes) \
    asm volatile("mbarrier.arrive.expect_tx.shared.b64 _, [%0], %1;" \
                 :: "r"((uint32_t)(mbar)), "r"((uint32_t)(bytes)) : "memory")
#define MBAR_ARRIVE(mbar) \
    asm volatile("mbarrier.arrive.shared.b64 _, [%0];" :: "r"((uint32_t)(mbar)) : "memory")
#define MBAR_WAIT(mbar, ph) do { \
    asm volatile("{\n\t.reg .pred P1;\n\t" \
        "WAIT_%=:\n\t" \
        "mbarrier.try_wait.parity.acquire.cta.shared::cta.b64 P1, [%0], %1, 0x989680;\n\t" \
        "@P1 bra.uni DONE_%=;\n\t" \
        "bra.uni WAIT_%=;\n\t" \
        "DONE_%=:\n\t}" :: "r"((uint32_t)(mbar)), "r"((uint32_t)(ph)) : "memory"); \
} while (0)

DI void tma2d(uint32_t dst, const CUtensorMap* map, int cx, int cy, uint32_t mbar) {
    asm volatile(
        "cp.async.bulk.tensor.2d.shared::cta.global.tile.mbarrier::complete_tx::bytes "
        "[%0], [%1, {%2, %3}], [%4];"
        :: "r"(dst), "l"(map), "r"(cx), "r"(cy), "r"(mbar) : "memory");
}

DI void ldsm4(uint32_t* r, uint32_t addr) {
    asm volatile("ldmatrix.sync.aligned.m8n8.x4.shared.b16 {%0,%1,%2,%3}, [%4];"
                 : "=r"(r[0]), "=r"(r[1]), "=r"(r[2]), "=r"(r[3]) : "r"(addr));
}

DI void mma16816(float* d, const uint32_t* a, const uint32_t* b) {
    asm volatile(
        "mma.sync.aligned.m16n8k16.row.col.f32.f16.f16.f32 "
        "{%0,%1,%2,%3}, {%4,%5,%6,%7}, {%8,%9}, {%0,%1,%2,%3};"
        : "+f"(d[0]), "+f"(d[1]), "+f"(d[2]), "+f"(d[3])
        : "r"(a[0]), "r"(a[1]), "r"(a[2]), "r"(a[3]), "r"(b[0]), "r"(b[1]));
}

// ---------------- codebook round (ties toward lower value, matching argmin) ----------------
DI float cb_round(float a) {
    // a >= 0 (possibly > 6; then -> 6, which equals clip-then-round)
    float q1 = ceilf(__fmaf_rn(2.0f, a, -0.5f)) * 0.5f;   // a in [0,2]: half-steps, tie-down
    float q2 = ceilf(a - 0.5f);                            // a in (2,4]: unit steps, tie-down
    float q3 = (a <= 5.0f) ? 4.0f : 6.0f;                  // a in (4,inf): 4 or 6, tie at 5 -> 4
    return (a <= 2.0f) ? q1 : ((a <= 4.0f) ? q2 : q3);
}

static constexpr int QUANT_BLOCKS = (N_DIM * K_DIM / 8) / 256;     //  8192
static constexpr int CONV_BLOCKS  = (M_DIM * K_DIM / 8) / 256;     // 16384

// ---------------- fused prep: W quantize (blocks 0..8191) + x->fp16 (rest) ----------------
__global__ void __launch_bounds__(256) prep_kernel(const float4* __restrict__ w4,
                                                   uint4* __restrict__ wdq,
                                                   const float4* __restrict__ x4,
                                                   uint4* __restrict__ xh) {
    if (blockIdx.x >= QUANT_BLOCKS) {
        // -------- x -> fp16 (memory-bound; fills around quant compute) --------
        const int t = (blockIdx.x - QUANT_BLOCKS) * 256 + threadIdx.x;
        float4 a = x4[2 * t], b = x4[2 * t + 1];
        __half2 h0 = __floats2half2_rn(a.x, a.y);
        __half2 h1 = __floats2half2_rn(a.z, a.w);
        __half2 h2 = __floats2half2_rn(b.x, b.y);
        __half2 h3 = __floats2half2_rn(b.z, b.w);
        uint4 o;
        o.x = *reinterpret_cast<uint32_t*>(&h0);
        o.y = *reinterpret_cast<uint32_t*>(&h1);
        o.z = *reinterpret_cast<uint32_t*>(&h2);
        o.w = *reinterpret_cast<uint32_t*>(&h3);
        xh[t] = o;
        return;
    }

    // -------- NVFP4 quantizer: 4 threads per 32-block, 8 elems/thread --------
    const int t = blockIdx.x * 256 + threadIdx.x;     // one thread = 8 elements
    const float4 va = w4[2 * t];
    const float4 vb = w4[2 * t + 1];
    float v[8]  = {va.x, va.y, va.z, va.w, vb.x, vb.y, vb.z, vb.w};
    float av[8];
    #pragma unroll
    for (int j = 0; j < 8; j++) av[j] = fabsf(v[j]);

    // block max over 32 elements = 4 threads (quad butterfly)
    float mx = av[0];
    #pragma unroll
    for (int j = 1; j < 8; j++) mx = fmaxf(mx, av[j]);
    mx = fmaxf(mx, __shfl_xor_sync(0xffffffffu, mx, 1));
    mx = fmaxf(mx, __shfl_xor_sync(0xffffffffu, mx, 2));
    const float bm = fmaxf(mx, 1e-12f);
    const float rinv = 1.0f / bm;                      // single division per thread

    // u[j]: magnitudes normalized to [0,1]; per-ratio scale is a compile-time const
    float u[8];
    #pragma unroll
    for (int j = 0; j < 8; j++) u[j] = av[j] * rinv;

    float best_mse = __int_as_float(0x7f800000);       // +inf
    float best_c = 0.0f, best_r = 0.0f;

    #pragma unroll
    for (int ti = 0; ti < 10; ti++) {
        const double rd = (ti == 9) ? 1.0 : (0.7 + (double)ti * (0.3 / 9.0));
        const float rf = (float)rd;                    // ratio (compile-time)
        const float c  = 6.0f / rf;                    // u -> codebook domain

        float e = 0.0f;
        #pragma unroll
        for (int j = 0; j < 8; j++) {
            float s = u[j] * c;                        // scaled magnitude
            float q = cb_round(s);
            float d = s - q;
            e = __fmaf_rn(d, d, e);
        }
        e += __shfl_xor_sync(0xffffffffu, e, 1);
        e += __shfl_xor_sync(0xffffffffu, e, 2);
        // domain factor (s6^2) folded: compare e * rf^2 (bm^2 common to all)
        float em = e * (rf * rf);
        if (em < best_mse) { best_mse = em; best_c = c; best_r = rf; }
    }

    // ue4m3 scale round-trip (matches reference astype(float8_e4m3fn))
    const float sf = (float)__nv_fp8_e4m3(bm * (best_r * (1.0f / 6.0f)));

    __half h[8];
    #pragma unroll
    for (int j = 0; j < 8; j++) {
        float q = copysignf(cb_round(u[j] * best_c), v[j]);
        h[j] = __float2half_rn(q * sf);                // <=5 significand bits: exact in fp16
    }
    uint4 o;
    o.x = *reinterpret_cast<uint32_t*>(&h[0]);
    o.y = *reinterpret_cast<uint32_t*>(&h[2]);
    o.z = *reinterpret_cast<uint32_t*>(&h[4]);
    o.w = *reinterpret_cast<uint32_t*>(&h[6]);
    wdq[t] = o;
}

// ---------------- persistent warp-specialized HMMA GEMM ----------------
// 148 CTAs x 288 threads: warps 0-7 consume (MMA), warp 8 is the TMA producer.
// Consumers release each smem slot right after their last ldmatrix (early
// empty-arrive), so refill overlaps the MMA tail of every chunk.
__global__ void __launch_bounds__(288, 1) gemm_kernel(
    const __grid_constant__ CUtensorMap tm_x,
    const __grid_constant__ CUtensorMap tm_w,
    const float* __restrict__ bias,
    float* __restrict__ out)
{
    extern __shared__ char smem_raw[];
    const uint32_t sb = (smem_u32(smem_raw) + 1023u) & ~1023u;   // 1KB align for SW128

    const int tid  = threadIdx.x;
    const int wid  = tid >> 5;
    const int lane = tid & 31;
    const int bid  = blockIdx.x;
    const int gsz  = gridDim.x;

    const int ntiles = (NTILES - bid + gsz - 1) / gsz;           // 6 or 7
    const uint32_t totalChunks = (uint32_t)ntiles * NCHUNKS;

    if (tid == 0) {
        #pragma unroll
        for (int s = 0; s < STAGES; s++) {
            MBAR_INIT(sb + OFF_FULL(s), 1);
            MBAR_INIT(sb + OFF_EMPTY(s), 8);     // 8 consumer warps arrive
        }
    }
    __syncthreads();

    if (wid == 8) {
        // ================= producer warp =================
        if (lane == 0) {
            // prologue: fill the first STAGES chunks of the first tile
            const int pm0 = (bid >> 4) * TILE_M;
            const int pn0 = (bid & 15) * TILE_N;
            #pragma unroll
            for (int f = 0; f < STAGES; f++) {
                MBAR_EXPECT_TX(sb + OFF_FULL(f), STAGE_BYTES);
                uint32_t st = sb + SMEM_CTRL + f * STAGE_BYTES;
                tma2d(st,           &tm_x, f * KCHUNK, pm0, sb + OFF_FULL(f));
                tma2d(st + A_BYTES, &tm_w, f * KCHUNK, pn0, sb + OFF_FULL(f));
            }
            // steady state: refill slot (f&3) once consumers drain chunk f-4
            #pragma unroll 1
            for (uint32_t f = STAGES; f < totalChunks; f++) {
                const uint32_t s  = f & (STAGES - 1);
                const uint32_t ph = ((f - STAGES) >> 2) & 1u;
                MBAR_WAIT(sb + OFF_EMPTY(s), ph);
                const int ftl = (int)(f >> 6);               // f / NCHUNKS
                const int fch = (int)(f & 63);
                const int ft  = bid + ftl * gsz;
                const int fm0 = (ft >> 4) * TILE_M;
                const int fn0 = (ft & 15) * TILE_N;
                MBAR_EXPECT_TX(sb + OFF_FULL(s), STAGE_BYTES);
                const uint32_t st = sb + SMEM_CTRL + s * STAGE_BYTES;
                tma2d(st,           &tm_x, fch * KCHUNK, fm0, sb + OFF_FULL(s));
                tma2d(st + A_BYTES, &tm_w, fch * KCHUNK, fn0, sb + OFF_FULL(s));
            }
        }
        return;
    }

    // ================= consumer warps (0-7) =================
    // per-thread ldmatrix addressing (SW128: physical = logical ^ ((row&7)<<4))
    const int sel = lane >> 3, l7 = lane & 7;
    const uint32_t xm = (uint32_t)l7 << 4;
    const int mwarp = (wid & 1) * 64;
    const int nwarp = (wid >> 1) * 64;
    const int rA = ((sel & 1) << 3) + l7;            // A: sel0,2 -> rows 0-7; sel1,3 -> rows 8-15
    const uint32_t kbA = (uint32_t)(sel >> 1) << 4;  // A: sel2,3 -> k+8 (16B)
    const int rB = (((sel >> 1) & 1) << 3) + l7;     // B: sel2,3 -> n+8
    const uint32_t kbB = (uint32_t)(sel & 1) << 4;   // B: sel1,3 -> k+8
    uint32_t rowA[4], rowB[4];
    #pragma unroll
    for (int f = 0; f < 4; f++) rowA[f] = (uint32_t)(mwarp + f * 16 + rA) * 128u;
    #pragma unroll
    for (int g = 0; g < 4; g++) rowB[g] = (uint32_t)(nwarp + g * 16 + rB) * 128u + (uint32_t)A_BYTES;

    // stagger kk start across same-SMSP warp pairs (wid and wid+4)
    const uint32_t kkoff = (uint32_t)((wid >> 2) << 1);

    uint32_t g = 0;                                  // global chunk counter (ring position)
    #pragma unroll 1
    for (int tl = 0; tl < ntiles; tl++) {
        const int t  = bid + tl * gsz;               // lockstep waves: good L2 tile sharing
        const int m0 = (t >> 4) * TILE_M;
        const int n0 = (t & 15) * TILE_N;

        float d[4][8][4] = {};

        #pragma unroll 1
        for (int i = 0; i < NCHUNKS; i++, g++) {
            const uint32_t s  = g & (STAGES - 1);
            const uint32_t ph = (g >> 2) & 1u;
            MBAR_WAIT(sb + OFF_FULL(s), ph);
            const uint32_t st = sb + SMEM_CTRL + s * STAGE_BYTES;

            #pragma unroll
            for (int kk = 0; kk < KCHUNK / 16; kk++) {
                const uint32_t kb = (((uint32_t)kk + kkoff) & 3u) << 5;   // staggered kk*32 bytes
                uint32_t bb[4][4], aa[4][4];
                #pragma unroll
                for (int gg = 0; gg < 4; gg++) ldsm4(bb[gg], st + rowB[gg] + ((kb + kbB) ^ xm));
                #pragma unroll
                for (int f = 0; f < 4; f++) ldsm4(aa[f], st + rowA[f] + ((kb + kbA) ^ xm));
                if (kk == 3) {
                    // all smem reads for this chunk issued -> release the slot early
                    __syncwarp();
                    if (lane == 0) MBAR_ARRIVE(sb + OFF_EMPTY(s));
                }
                #pragma unroll
                for (int f = 0; f < 4; f++)
                    #pragma unroll
                    for (int gg = 0; gg < 4; gg++) {
                        mma16816(d[f][2 * gg],     aa[f], &bb[gg][0]);
                        mma16816(d[f][2 * gg + 1], aa[f], &bb[gg][2]);
                    }
            }
        }

        // ---- epilogue: registers -> gmem, add bias (overlaps next tile's TMAs) ----
        const int g2 = lane >> 2, tg = lane & 3;
        float bv0[8], bv1[8];
        #pragma unroll
        for (int nf = 0; nf < 8; nf++) {
            const int n = n0 + nwarp + nf * 8 + tg * 2;
            bv0[nf] = bias[n];
            bv1[nf] = bias[n + 1];
        }
        #pragma unroll
        for (int f = 0; f < 4; f++) {
            const int mrow = m0 + mwarp + f * 16 + g2;
            #pragma unroll
            for (int nf = 0; nf < 8; nf++) {
                const int n = n0 + nwarp + nf * 8 + tg * 2;
                float2 v0 = make_float2(d[f][nf][0] + bv0[nf], d[f][nf][1] + bv1[nf]);
                float2 v1 = make_float2(d[f][nf][2] + bv0[nf], d[f][nf][3] + bv1[nf]);
                *reinterpret_cast<float2*>(&out[(size_t)mrow * N_DIM + n]) = v0;
                *reinterpret_cast<float2*>(&out[(size_t)(mrow + 8) * N_DIM + n]) = v1;
            }
        }
    }
}

// ---------------- host ----------------
typedef CUresult (*PFN_EncodeTiled)(
    CUtensorMap*, CUtensorMapDataType, cuuint32_t, void*,
    const cuuint64_t*, const cuuint64_t*, const cuuint32_t*, const cuuint32_t*,
    CUtensorMapInterleave, CUtensorMapSwizzle, CUtensorMapL2promotion, CUtensorMapFloatOOBfill);

static void make_map_2d(PFN_EncodeTiled fn, CUtensorMap* m, void* ptr,
                        uint64_t rows, uint32_t boxRows) {
    cuuint64_t dims[2]    = {(cuuint64_t)K_DIM, (cuuint64_t)rows};
    cuuint64_t strides[1] = {(cuuint64_t)K_DIM * 2};
    cuuint32_t box[2]     = {(cuuint32_t)KCHUNK, boxRows};   // 64 fp16 = 128B (SW128 limit)
    cuuint32_t es[2]      = {1, 1};
    fn(m, CU_TENSOR_MAP_DATA_TYPE_FLOAT16, 2, ptr, dims, strides, box, es,
       CU_TENSOR_MAP_INTERLEAVE_NONE, CU_TENSOR_MAP_SWIZZLE_128B,
       CU_TENSOR_MAP_L2_PROMOTION_L2_128B, CU_TENSOR_MAP_FLOAT_OOB_FILL_NONE);
}

extern "C" void kernel_launch(void* const* d_in, const int* in_sizes, int n_in,
                              void* d_out, int out_size) {
    const float* x    = (const float*)d_in[0];
    const float* w    = (const float*)d_in[1];
    const float* bias = (const float*)d_in[2];
    float* out = (float*)d_out;

    void *p_wdq, *p_xh;
    cudaGetSymbolAddress(&p_wdq, g_wdq);
    cudaGetSymbolAddress(&p_xh, g_xh);

    // 1) fused: quantize W -> exact fp16 plane, convert x -> fp16
    prep_kernel<<<QUANT_BLOCKS + CONV_BLOCKS, 256>>>(
        (const float4*)w, (uint4*)p_wdq, (const float4*)x, (uint4*)p_xh);

    // 2) tensor maps (host-side; happens at graph-capture time, free at replay)
    PFN_EncodeTiled fn = nullptr;
    cudaDriverEntryPointQueryResult qres;
    cudaGetDriverEntryPointByVersion("cuTensorMapEncodeTiled", (void**)&fn, 12000,
                                     cudaEnableDefault, &qres);
    if (!fn) return;

    CUtensorMap tm_x, tm_w;
    make_map_2d(fn, &tm_x, p_xh,  M_DIM, TILE_M);
    make_map_2d(fn, &tm_w, p_wdq, N_DIM, TILE_N);

    cudaFuncSetAttribute(gemm_kernel, cudaFuncAttributeMaxDynamicSharedMemorySize, SMEM_REQ);
    gemm_kernel<<<GRID_SM, 288, SMEM_REQ>>>(tm_x, tm_w, bias, out);
}

// round 8
// speedup vs baseline: 1.0677x; 1.0677x over previous
#include <cuda_runtime.h>
#include <cuda.h>
#include <cuda_fp16.h>
#include <cuda_fp8.h>
#include <cstdint>

#define DI __device__ __forceinline__

// ---------------- problem dims ----------------
static constexpr int M_DIM = 8192;
static constexpr int N_DIM = 4096;
static constexpr int K_DIM = 4096;

// ---------------- GEMM tiling ----------------
static constexpr int TILE_M = 128;
static constexpr int TILE_N = 256;
static constexpr int KCHUNK = 64;                      // fp16 elems per k-chunk (128B rows, SW128)
static constexpr int NCHUNKS = K_DIM / KCHUNK;         // 64
static constexpr int STAGES  = 4;
static constexpr int NTILES  = (M_DIM / TILE_M) * (N_DIM / TILE_N);  // 1024
static constexpr int GRID_SM = 148;                    // persistent CTAs (1/SM)
static constexpr int A_BYTES = TILE_M * KCHUNK * 2;    // 16 KB
static constexpr int B_BYTES = TILE_N * KCHUNK * 2;    // 32 KB
static constexpr int STAGE_BYTES = A_BYTES + B_BYTES;  // 48 KB
static constexpr int SMEM_CTRL  = 1024;
static constexpr int SMEM_REQ   = SMEM_CTRL + STAGES * STAGE_BYTES + 1024;  // ~199 KB

#define OFF_FULL(s)  ((s)*16)
#define OFF_EMPTY(s) ((s)*16 + 8)

// ---------------- device scratch (no cudaMalloc allowed) ----------------
__device__ __align__(1024) __half g_wdq[(size_t)N_DIM * K_DIM];   // 32 MB
__device__ __align__(1024) __half g_xh[(size_t)M_DIM * K_DIM];    // 64 MB

// ---------------- PTX helpers ----------------
DI uint32_t smem_u32(const void* p) {
    uint32_t a;
    asm("{ .reg .u64 t; cvta.to.shared.u64 t, %1; cvt.u32.u64 %0, t; }" : "=r"(a) : "l"(p));
    return a;
}

#define MBAR_INIT(mbar, cnt) \
    asm volatile("mbarrier.init.shared.b64 [%0], %1;" :: "r"((uint32_t)(mbar)), "r"((uint32_t)(cnt)) : "memory")
#define MBAR_EXPECT_TX(mbar, bytes) \
    asm volatile("mbarrier.arrive.expect_tx.shared.b64 _, [%0], %1;" \
                 :: "r"((uint32_t)(mbar)), "r"((uint32_t)(bytes)) : "memory")
#define MBAR_ARRIVE(mbar) \
    asm volatile("mbarrier.arrive.shared.b64 _, [%0];" :: "r"((uint32_t)(mbar)) : "memory")
#define MBAR_WAIT(mbar, ph) do { \
    asm volatile("{\n\t.reg .pred P1;\n\t" \
        "WAIT_%=:\n\t" \
        "mbarrier.try_wait.parity.acquire.cta.shared::cta.b64 P1, [%0], %1, 0x989680;\n\t" \
        "@P1 bra.uni DONE_%=;\n\t" \
        "bra.uni WAIT_%=;\n\t" \
        "DONE_%=:\n\t}" :: "r"((uint32_t)(mbar)), "r"((uint32_t)(ph)) : "memory"); \
} while (0)

DI void tma2d(uint32_t dst, const CUtensorMap* map, int cx, int cy, uint32_t mbar) {
    asm volatile(
        "cp.async.bulk.tensor.2d.shared::cta.global.tile.mbarrier::complete_tx::bytes "
        "[%0], [%1, {%2, %3}], [%4];"
        :: "r"(dst), "l"(map), "r"(cx), "r"(cy), "r"(mbar) : "memory");
}

DI void ldsm4(uint32_t* r, uint32_t addr) {
    asm volatile("ldmatrix.sync.aligned.m8n8.x4.shared.b16 {%0,%1,%2,%3}, [%4];"
                 : "=r"(r[0]), "=r"(r[1]), "=r"(r[2]), "=r"(r[3]) : "r"(addr));
}

DI void mma16816(float* d, const uint32_t* a, const uint32_t* b) {
    asm volatile(
        "mma.sync.aligned.m16n8k16.row.col.f32.f16.f16.f32 "
        "{%0,%1,%2,%3}, {%4,%5,%6,%7}, {%8,%9}, {%0,%1,%2,%3};"
        : "+f"(d[0]), "+f"(d[1]), "+f"(d[2]), "+f"(d[3])
        : "r"(a[0]), "r"(a[1]), "r"(a[2]), "r"(a[3]), "r"(b[0]), "r"(b[1]));
}

// ---------------- codebook round (ties toward lower value, matching argmin) ----------------
DI float cb_round(float a) {
    // a >= 0 (possibly > 6; then -> 6, which equals clip-then-round)
    float q1 = ceilf(__fmaf_rn(2.0f, a, -0.5f)) * 0.5f;   // a in [0,2]: half-steps, tie-down
    float q2 = ceilf(a - 0.5f);                            // a in (2,4]: unit steps, tie-down
    float q3 = (a <= 5.0f) ? 4.0f : 6.0f;                  // a in (4,inf): 4 or 6, tie at 5 -> 4
    return (a <= 2.0f) ? q1 : ((a <= 4.0f) ? q2 : q3);
}

static constexpr int QUANT_BLOCKS = (N_DIM * K_DIM / 8) / 256;     //  8192
static constexpr int CONV_BLOCKS  = (M_DIM * K_DIM / 8) / 256;     // 16384

// ---------------- fused prep: W quantize (blocks 0..8191) + x->fp16 (rest) ----------------
__global__ void __launch_bounds__(256) prep_kernel(const float4* __restrict__ w4,
                                                   uint4* __restrict__ wdq,
                                                   const float4* __restrict__ x4,
                                                   uint4* __restrict__ xh) {
    if (blockIdx.x >= QUANT_BLOCKS) {
        // -------- x -> fp16 (memory-bound; fills around quant compute) --------
        const int t = (blockIdx.x - QUANT_BLOCKS) * 256 + threadIdx.x;
        float4 a = x4[2 * t], b = x4[2 * t + 1];
        __half2 h0 = __floats2half2_rn(a.x, a.y);
        __half2 h1 = __floats2half2_rn(a.z, a.w);
        __half2 h2 = __floats2half2_rn(b.x, b.y);
        __half2 h3 = __floats2half2_rn(b.z, b.w);
        uint4 o;
        o.x = *reinterpret_cast<uint32_t*>(&h0);
        o.y = *reinterpret_cast<uint32_t*>(&h1);
        o.z = *reinterpret_cast<uint32_t*>(&h2);
        o.w = *reinterpret_cast<uint32_t*>(&h3);
        xh[t] = o;
        return;
    }

    // -------- NVFP4 quantizer: 4 threads per 32-block, 8 elems/thread --------
    const int t = blockIdx.x * 256 + threadIdx.x;     // one thread = 8 elements
    const float4 va = w4[2 * t];
    const float4 vb = w4[2 * t + 1];
    float v[8]  = {va.x, va.y, va.z, va.w, vb.x, vb.y, vb.z, vb.w};
    float av[8];
    #pragma unroll
    for (int j = 0; j < 8; j++) av[j] = fabsf(v[j]);

    // block max over 32 elements = 4 threads (quad butterfly)
    float mx = av[0];
    #pragma unroll
    for (int j = 1; j < 8; j++) mx = fmaxf(mx, av[j]);
    mx = fmaxf(mx, __shfl_xor_sync(0xffffffffu, mx, 1));
    mx = fmaxf(mx, __shfl_xor_sync(0xffffffffu, mx, 2));
    const float bm = fmaxf(mx, 1e-12f);
    const float rinv = 1.0f / bm;                      // single division per thread

    // u[j]: magnitudes normalized to [0,1]; per-ratio scale is a compile-time const
    float u[8];
    #pragma unroll
    for (int j = 0; j < 8; j++) u[j] = av[j] * rinv;

    float best_mse = __int_as_float(0x7f800000);       // +inf
    float best_c = 0.0f, best_r = 0.0f;

    #pragma unroll
    for (int ti = 0; ti < 10; ti++) {
        const double rd = (ti == 9) ? 1.0 : (0.7 + (double)ti * (0.3 / 9.0));
        const float rf = (float)rd;                    // ratio (compile-time)
        const float c  = 6.0f / rf;                    // u -> codebook domain

        float e = 0.0f;
        #pragma unroll
        for (int j = 0; j < 8; j++) {
            float s = u[j] * c;                        // scaled magnitude
            float q = cb_round(s);
            float d = s - q;
            e = __fmaf_rn(d, d, e);
        }
        e += __shfl_xor_sync(0xffffffffu, e, 1);
        e += __shfl_xor_sync(0xffffffffu, e, 2);
        // domain factor (s6^2) folded: compare e * rf^2 (bm^2 common to all)
        float em = e * (rf * rf);
        if (em < best_mse) { best_mse = em; best_c = c; best_r = rf; }
    }

    // ue4m3 scale round-trip (matches reference astype(float8_e4m3fn))
    const float sf = (float)__nv_fp8_e4m3(bm * (best_r * (1.0f / 6.0f)));

    __half h[8];
    #pragma unroll
    for (int j = 0; j < 8; j++) {
        float q = copysignf(cb_round(u[j] * best_c), v[j]);
        h[j] = __float2half_rn(q * sf);                // <=5 significand bits: exact in fp16
    }
    uint4 o;
    o.x = *reinterpret_cast<uint32_t*>(&h[0]);
    o.y = *reinterpret_cast<uint32_t*>(&h[2]);
    o.z = *reinterpret_cast<uint32_t*>(&h[4]);
    o.w = *reinterpret_cast<uint32_t*>(&h[6]);
    wdq[t] = o;
}

// ---------------- persistent HMMA GEMM: out[M,N] = xh[M,K] @ wdq[N,K]^T + bias ----------------
// 148 CTAs x 512 threads (16 warps, warp tile 64x32): 4 warps per SMSP so ldsm
// load-phases of one warp hide under MMA phases of the others. Ring/barrier
// structure identical to the proven round-6 kernel.
__global__ void __launch_bounds__(512, 1) gemm_kernel(
    const __grid_constant__ CUtensorMap tm_x,
    const __grid_constant__ CUtensorMap tm_w,
    const float* __restrict__ bias,
    float* __restrict__ out)
{
    extern __shared__ char smem_raw[];
    const uint32_t sb = (smem_u32(smem_raw) + 1023u) & ~1023u;   // 1KB align for SW128

    const int tid  = threadIdx.x;
    const int wid  = tid >> 5;
    const int lane = tid & 31;
    const int bid  = blockIdx.x;
    const int gsz  = gridDim.x;

    const int ntiles = (NTILES - bid + gsz - 1) / gsz;           // 6 or 7
    const uint32_t totalChunks = (uint32_t)ntiles * NCHUNKS;

    if (tid == 0) {
        #pragma unroll
        for (int s = 0; s < STAGES; s++) {
            MBAR_INIT(sb + OFF_FULL(s), 1);
            MBAR_INIT(sb + OFF_EMPTY(s), 16);    // 16 warps arrive
        }
    }
    __syncthreads();

    // prologue: fill the first STAGES chunks of my first tile
    if (tid == 0) {
        const int pm0 = (bid >> 4) * TILE_M;
        const int pn0 = (bid & 15) * TILE_N;
        #pragma unroll
        for (int f = 0; f < STAGES; f++) {
            MBAR_EXPECT_TX(sb + OFF_FULL(f), STAGE_BYTES);
            uint32_t st = sb + SMEM_CTRL + f * STAGE_BYTES;
            tma2d(st,           &tm_x, f * KCHUNK, pm0, sb + OFF_FULL(f));
            tma2d(st + A_BYTES, &tm_w, f * KCHUNK, pn0, sb + OFF_FULL(f));
        }
    }

    // per-thread ldmatrix addressing (SW128: physical = logical ^ ((row&7)<<4))
    const int sel = lane >> 3, l7 = lane & 7;
    const uint32_t xm = (uint32_t)l7 << 4;
    const int mwarp = (wid & 1) * 64;                // 2 warps across M
    const int nwarp = (wid >> 1) * 32;               // 8 warps across N
    const int rA = ((sel & 1) << 3) + l7;            // A: sel0,2 -> rows 0-7; sel1,3 -> rows 8-15
    const uint32_t kbA = (uint32_t)(sel >> 1) << 4;  // A: sel2,3 -> k+8 (16B)
    const int rB = (((sel >> 1) & 1) << 3) + l7;     // B: sel2,3 -> n+8
    const uint32_t kbB = (uint32_t)(sel & 1) << 4;   // B: sel1,3 -> k+8
    uint32_t rowA[4], rowB[2];
    #pragma unroll
    for (int f = 0; f < 4; f++) rowA[f] = (uint32_t)(mwarp + f * 16 + rA) * 128u;
    #pragma unroll
    for (int g = 0; g < 2; g++) rowB[g] = (uint32_t)(nwarp + g * 16 + rB) * 128u + (uint32_t)A_BYTES;

    uint32_t g = 0;                                  // global chunk counter (ring position)
    #pragma unroll 1
    for (int tl = 0; tl < ntiles; tl++) {
        const int t  = bid + tl * gsz;               // lockstep waves: good L2 tile sharing
        const int m0 = (t >> 4) * TILE_M;
        const int n0 = (t & 15) * TILE_N;

        float d[4][4][4] = {};

        #pragma unroll 1
        for (int i = 0; i < NCHUNKS; i++, g++) {
            const uint32_t s  = g & (STAGES - 1);
            const uint32_t ph = (g >> 2) & 1u;
            MBAR_WAIT(sb + OFF_FULL(s), ph);
            const uint32_t st = sb + SMEM_CTRL + s * STAGE_BYTES;

            #pragma unroll
            for (int kk = 0; kk < KCHUNK / 16; kk++) {
                const uint32_t kb = (uint32_t)kk << 5;          // kk*32 bytes
                uint32_t bb[2][4], aa[4][4];
                #pragma unroll
                for (int gg = 0; gg < 2; gg++) ldsm4(bb[gg], st + rowB[gg] + ((kb + kbB) ^ xm));
                #pragma unroll
                for (int f = 0; f < 4; f++) ldsm4(aa[f], st + rowA[f] + ((kb + kbA) ^ xm));
                #pragma unroll
                for (int f = 0; f < 4; f++)
                    #pragma unroll
                    for (int gg = 0; gg < 2; gg++) {
                        mma16816(d[f][2 * gg],     aa[f], &bb[gg][0]);
                        mma16816(d[f][2 * gg + 1], aa[f], &bb[gg][2]);
                    }
            }

            __syncwarp();
            if (lane == 0) MBAR_ARRIVE(sb + OFF_EMPTY(s));

            if (tid == 0 && g + STAGES < totalChunks) {
                MBAR_WAIT(sb + OFF_EMPTY(s), ph);               // completion #(g>>2) on this slot
                const uint32_t f  = g + STAGES;
                const int ftl     = (int)(f >> 6);              // f / NCHUNKS
                const int fch     = (int)(f & 63);
                const int ft      = bid + ftl * gsz;
                const int fm0     = (ft >> 4) * TILE_M;
                const int fn0     = (ft & 15) * TILE_N;
                MBAR_EXPECT_TX(sb + OFF_FULL(s), STAGE_BYTES);
                tma2d(st,           &tm_x, fch * KCHUNK, fm0, sb + OFF_FULL(s));
                tma2d(st + A_BYTES, &tm_w, fch * KCHUNK, fn0, sb + OFF_FULL(s));
            }
        }

        // ---- epilogue: registers -> gmem, add bias (overlaps next tile's TMAs) ----
        const int g2 = lane >> 2, tg = lane & 3;
        float bv0[4], bv1[4];
        #pragma unroll
        for (int nf = 0; nf < 4; nf++) {
            const int n = n0 + nwarp + nf * 8 + tg * 2;
            bv0[nf] = bias[n];
            bv1[nf] = bias[n + 1];
        }
        #pragma unroll
        for (int f = 0; f < 4; f++) {
            const int mrow = m0 + mwarp + f * 16 + g2;
            #pragma unroll
            for (int nf = 0; nf < 4; nf++) {
                const int n = n0 + nwarp + nf * 8 + tg * 2;
                float2 v0 = make_float2(d[f][nf][0] + bv0[nf], d[f][nf][1] + bv1[nf]);
                float2 v1 = make_float2(d[f][nf][2] + bv0[nf], d[f][nf][3] + bv1[nf]);
                *reinterpret_cast<float2*>(&out[(size_t)mrow * N_DIM + n]) = v0;
                *reinterpret_cast<float2*>(&out[(size_t)(mrow + 8) * N_DIM + n]) = v1;
            }
        }
    }
}

// ---------------- host ----------------
typedef CUresult (*PFN_EncodeTiled)(
    CUtensorMap*, CUtensorMapDataType, cuuint32_t, void*,
    const cuuint64_t*, const cuuint64_t*, const cuuint32_t*, const cuuint32_t*,
    CUtensorMapInterleave, CUtensorMapSwizzle, CUtensorMapL2promotion, CUtensorMapFloatOOBfill);

static void make_map_2d(PFN_EncodeTiled fn, CUtensorMap* m, void* ptr,
                        uint64_t rows, uint32_t boxRows) {
    cuuint64_t dims[2]    = {(cuuint64_t)K_DIM, (cuuint64_t)rows};
    cuuint64_t strides[1] = {(cuuint64_t)K_DIM * 2};
    cuuint32_t box[2]     = {(cuuint32_t)KCHUNK, boxRows};   // 64 fp16 = 128B (SW128 limit)
    cuuint32_t es[2]      = {1, 1};
    fn(m, CU_TENSOR_MAP_DATA_TYPE_FLOAT16, 2, ptr, dims, strides, box, es,
       CU_TENSOR_MAP_INTERLEAVE_NONE, CU_TENSOR_MAP_SWIZZLE_128B,
       CU_TENSOR_MAP_L2_PROMOTION_L2_128B, CU_TENSOR_MAP_FLOAT_OOB_FILL_NONE);
}

extern "C" void kernel_launch(void* const* d_in, const int* in_sizes, int n_in,
                              void* d_out, int out_size) {
    const float* x    = (const float*)d_in[0];
    const float* w    = (const float*)d_in[1];
    const float* bias = (const float*)d_in[2];
    float* out = (float*)d_out;

    void *p_wdq, *p_xh;
    cudaGetSymbolAddress(&p_wdq, g_wdq);
    cudaGetSymbolAddress(&p_xh, g_xh);

    // 1) fused: quantize W -> exact fp16 plane, convert x -> fp16
    prep_kernel<<<QUANT_BLOCKS + CONV_BLOCKS, 256>>>(
        (const float4*)w, (uint4*)p_wdq, (const float4*)x, (uint4*)p_xh);

    // 2) tensor maps (host-side; happens at graph-capture time, free at replay)
    PFN_EncodeTiled fn = nullptr;
    cudaDriverEntryPointQueryResult qres;
    cudaGetDriverEntryPointByVersion("cuTensorMapEncodeTiled", (void**)&fn, 12000,
                                     cudaEnableDefault, &qres);
    if (!fn) return;

    CUtensorMap tm_x, tm_w;
    make_map_2d(fn, &tm_x, p_xh,  M_DIM, TILE_M);
    make_map_2d(fn, &tm_w, p_wdq, N_DIM, TILE_N);

    cudaFuncSetAttribute(gemm_kernel, cudaFuncAttributeMaxDynamicSharedMemorySize, SMEM_REQ);
    gemm_kernel<<<GRID_SM, 512, SMEM_REQ>>>(tm_x, tm_w, bias, out);
}

// round 9
// speedup vs baseline: 1.0848x; 1.0160x over previous
#include <cuda_runtime.h>
#include <cuda.h>
#include <cuda_fp16.h>
#include <cuda_fp8.h>
#include <cstdint>

#define DI __device__ __forceinline__

// ---------------- problem dims ----------------
static constexpr int M_DIM = 8192;
static constexpr int N_DIM = 4096;
static constexpr int K_DIM = 4096;

// ---------------- GEMM tiling ----------------
static constexpr int TILE_M = 128;
static constexpr int TILE_N = 256;
static constexpr int KCHUNK = 64;                      // fp16 elems per k-chunk (128B rows, SW128)
static constexpr int NCHUNKS = K_DIM / KCHUNK;         // 64
static constexpr int STAGES  = 4;
static constexpr int NTILES  = (M_DIM / TILE_M) * (N_DIM / TILE_N);  // 1024
static constexpr int GRID_SM = 148;                    // persistent CTAs (1/SM)
static constexpr int A_BYTES = TILE_M * KCHUNK * 2;    // 16 KB
static constexpr int B_BYTES = TILE_N * KCHUNK * 2;    // 32 KB
static constexpr int STAGE_BYTES = A_BYTES + B_BYTES;  // 48 KB
static constexpr int SMEM_CTRL  = 1024;
static constexpr int SMEM_REQ   = SMEM_CTRL + STAGES * STAGE_BYTES + 1024;  // ~199 KB

#define OFF_FULL(s)  ((s)*16)
#define OFF_EMPTY(s) ((s)*16 + 8)

// ---------------- device scratch (no cudaMalloc allowed) ----------------
__device__ __align__(1024) __half g_wdq[(size_t)N_DIM * K_DIM];   // 32 MB
__device__ __align__(1024) __half g_xh[(size_t)M_DIM * K_DIM];    // 64 MB

// ---------------- PTX helpers ----------------
DI uint32_t smem_u32(const void* p) {
    uint32_t a;
    asm("{ .reg .u64 t; cvta.to.shared.u64 t, %1; cvt.u32.u64 %0, t; }" : "=r"(a) : "l"(p));
    return a;
}

#define MBAR_INIT(mbar, cnt) \
    asm volatile("mbarrier.init.shared.b64 [%0], %1;" :: "r"((uint32_t)(mbar)), "r"((uint32_t)(cnt)) : "memory")
#define MBAR_EXPECT_TX(mbar, bytes) \
    asm volatile("mbarrier.arrive.expect_tx.shared.b64 _, [%0], %1;" \
                 :: "r"((uint32_t)(mbar)), "r"((uint32_t)(bytes)) : "memory")
#define MBAR_ARRIVE(mbar) \
    asm volatile("mbarrier.arrive.shared.b64 _, [%0];" :: "r"((uint32_t)(mbar)) : "memory")
#define MBAR_WAIT(mbar, ph) do { \
    asm volatile("{\n\t.reg .pred P1;\n\t" \
        "WAIT_%=:\n\t" \
        "mbarrier.try_wait.parity.acquire.cta.shared::cta.b64 P1, [%0], %1, 0x989680;\n\t" \
        "@P1 bra.uni DONE_%=;\n\t" \
        "bra.uni WAIT_%=;\n\t" \
        "DONE_%=:\n\t}" :: "r"((uint32_t)(mbar)), "r"((uint32_t)(ph)) : "memory"); \
} while (0)

DI void tma2d(uint32_t dst, const CUtensorMap* map, int cx, int cy, uint32_t mbar) {
    asm volatile(
        "cp.async.bulk.tensor.2d.shared::cta.global.tile.mbarrier::complete_tx::bytes "
        "[%0], [%1, {%2, %3}], [%4];"
        :: "r"(dst), "l"(map), "r"(cx), "r"(cy), "r"(mbar) : "memory");
}

DI void ldsm4(uint32_t* r, uint32_t addr) {
    asm volatile("ldmatrix.sync.aligned.m8n8.x4.shared.b16 {%0,%1,%2,%3}, [%4];"
                 : "=r"(r[0]), "=r"(r[1]), "=r"(r[2]), "=r"(r[3]) : "r"(addr));
}

DI void mma16816(float* d, const uint32_t* a, const uint32_t* b) {
    asm volatile(
        "mma.sync.aligned.m16n8k16.row.col.f32.f16.f16.f32 "
        "{%0,%1,%2,%3}, {%4,%5,%6,%7}, {%8,%9}, {%0,%1,%2,%3};"
        : "+f"(d[0]), "+f"(d[1]), "+f"(d[2]), "+f"(d[3])
        : "r"(a[0]), "r"(a[1]), "r"(a[2]), "r"(a[3]), "r"(b[0]), "r"(b[1]));
}

// ---------------- unified codebook round in p = 2s domain ----------------
// codebook (p-domain): {0,1,2,3,4,6,8,12}; tie-down via ceil(x-0.5).
// q = min(2^k * ceil(p*2^-k - 0.5), 12), k = 0 (p<=4), 1 (p<=8), 2 (p>8).
// Bit-identical to the old 3-branch cb_round (verified at all boundaries/ties).
DI float cbp_round(float p) {
    const bool r0 = (p <= 4.0f);
    const bool r1 = (p <= 8.0f);
    const float is = r0 ? 1.0f : (r1 ? 0.5f : 0.25f);
    const float sc = r0 ? 1.0f : (r1 ? 2.0f : 4.0f);
    float cr = ceilf(__fmaf_rn(is, p, -0.5f));
    return fminf(cr * sc, 12.0f);
}

static constexpr int QUANT_BLOCKS = (N_DIM * K_DIM / 8) / 256;     //  8192
static constexpr int CONV_BLOCKS  = (M_DIM * K_DIM / 8) / 256;     // 16384

// ---------------- fused prep: W quantize (blocks 0..8191) + x->fp16 (rest) ----------------
__global__ void __launch_bounds__(256) prep_kernel(const float4* __restrict__ w4,
                                                   uint4* __restrict__ wdq,
                                                   const float4* __restrict__ x4,
                                                   uint4* __restrict__ xh) {
    if (blockIdx.x >= QUANT_BLOCKS) {
        // -------- x -> fp16 (memory-bound; fills around quant compute) --------
        const int t = (blockIdx.x - QUANT_BLOCKS) * 256 + threadIdx.x;
        float4 a = x4[2 * t], b = x4[2 * t + 1];
        __half2 h0 = __floats2half2_rn(a.x, a.y);
        __half2 h1 = __floats2half2_rn(a.z, a.w);
        __half2 h2 = __floats2half2_rn(b.x, b.y);
        __half2 h3 = __floats2half2_rn(b.z, b.w);
        uint4 o;
        o.x = *reinterpret_cast<uint32_t*>(&h0);
        o.y = *reinterpret_cast<uint32_t*>(&h1);
        o.z = *reinterpret_cast<uint32_t*>(&h2);
        o.w = *reinterpret_cast<uint32_t*>(&h3);
        xh[t] = o;
        return;
    }

    // -------- NVFP4 quantizer: 4 threads per 32-block, 8 elems/thread --------
    const int t = blockIdx.x * 256 + threadIdx.x;     // one thread = 8 elements
    const float4 va = w4[2 * t];
    const float4 vb = w4[2 * t + 1];
    float v[8]  = {va.x, va.y, va.z, va.w, vb.x, vb.y, vb.z, vb.w};
    float av[8];
    #pragma unroll
    for (int j = 0; j < 8; j++) av[j] = fabsf(v[j]);

    // block max over 32 elements = 4 threads (quad butterfly)
    float mx = av[0];
    #pragma unroll
    for (int j = 1; j < 8; j++) mx = fmaxf(mx, av[j]);
    mx = fmaxf(mx, __shfl_xor_sync(0xffffffffu, mx, 1));
    mx = fmaxf(mx, __shfl_xor_sync(0xffffffffu, mx, 2));
    const float bm = fmaxf(mx, 1e-12f);
    const float rinv = 1.0f / bm;                      // single division per thread
    const float rinv2 = rinv + rinv;                   // exact x2

    // pb[j] = 2*|v|/bm in [0,2]; per-ratio scale is a compile-time const
    float pb[8];
    #pragma unroll
    for (int j = 0; j < 8; j++) pb[j] = av[j] * rinv2;

    float best_mse = __int_as_float(0x7f800000);       // +inf
    float best_c = 0.0f, best_r = 0.0f;

    #pragma unroll
    for (int ti = 0; ti < 10; ti++) {
        const double rd = (ti == 9) ? 1.0 : (0.7 + (double)ti * (0.3 / 9.0));
        const float rf = (float)rd;                    // ratio (compile-time)
        const float c  = 6.0f / rf;                    // p -> codebook (p) domain

        float e = 0.0f;
        #pragma unroll
        for (int j = 0; j < 8; j++) {
            float pp = pb[j] * c;                      // = 2*s, exact 2x of old s
            float q  = cbp_round(pp);
            float d  = pp - q;                         // = 2*(s - q_s)
            e = __fmaf_rn(d, d, e);                    // accumulates 4x old e (uniform)
        }
        e += __shfl_xor_sync(0xffffffffu, e, 1);
        e += __shfl_xor_sync(0xffffffffu, e, 2);
        // compare e * rf^2 (uniform 4x and bm^2 factors preserve argmin)
        float em = e * (rf * rf);
        if (em < best_mse) { best_mse = em; best_c = c; best_r = rf; }
    }

    // ue4m3 scale round-trip (matches reference astype(float8_e4m3fn))
    const float sf  = (float)__nv_fp8_e4m3(bm * (best_r * (1.0f / 6.0f)));
    const float hsf = 0.5f * sf;                       // exact halving (p-domain -> value)

    __half h[8];
    #pragma unroll
    for (int j = 0; j < 8; j++) {
        float q = cbp_round(pb[j] * best_c);           // exact tie-down, p-domain
        h[j] = __float2half_rn(copysignf(q * hsf, v[j]));  // <=5 sig bits: exact in fp16
    }
    uint4 o;
    o.x = *reinterpret_cast<uint32_t*>(&h[0]);
    o.y = *reinterpret_cast<uint32_t*>(&h[2]);
    o.z = *reinterpret_cast<uint32_t*>(&h[4]);
    o.w = *reinterpret_cast<uint32_t*>(&h[6]);
    wdq[t] = o;
}

// ---------------- persistent HMMA GEMM: out[M,N] = xh[M,K] @ wdq[N,K]^T + bias ----------------
// Proven round-6 configuration: 148 CTAs x 256 threads, 8 warps, warp tile 64x64,
// continuous TMA ring across tile boundaries (fill paid once, epilogue overlaps prefetch).
__global__ void __launch_bounds__(256, 1) gemm_kernel(
    const __grid_constant__ CUtensorMap tm_x,
    const __grid_constant__ CUtensorMap tm_w,
    const float* __restrict__ bias,
    float* __restrict__ out)
{
    extern __shared__ char smem_raw[];
    const uint32_t sb = (smem_u32(smem_raw) + 1023u) & ~1023u;   // 1KB align for SW128

    const int tid  = threadIdx.x;
    const int wid  = tid >> 5;
    const int lane = tid & 31;
    const int bid  = blockIdx.x;
    const int gsz  = gridDim.x;

    const int ntiles = (NTILES - bid + gsz - 1) / gsz;           // 6 or 7
    const uint32_t totalChunks = (uint32_t)ntiles * NCHUNKS;

    if (tid == 0) {
        #pragma unroll
        for (int s = 0; s < STAGES; s++) {
            MBAR_INIT(sb + OFF_FULL(s), 1);
            MBAR_INIT(sb + OFF_EMPTY(s), 8);     // 8 warps arrive
        }
    }
    __syncthreads();

    // prologue: fill the first STAGES chunks of my first tile
    if (tid == 0) {
        const int pm0 = (bid >> 4) * TILE_M;
        const int pn0 = (bid & 15) * TILE_N;
        #pragma unroll
        for (int f = 0; f < STAGES; f++) {
            MBAR_EXPECT_TX(sb + OFF_FULL(f), STAGE_BYTES);
            uint32_t st = sb + SMEM_CTRL + f * STAGE_BYTES;
            tma2d(st,           &tm_x, f * KCHUNK, pm0, sb + OFF_FULL(f));
            tma2d(st + A_BYTES, &tm_w, f * KCHUNK, pn0, sb + OFF_FULL(f));
        }
    }

    // per-thread ldmatrix addressing (SW128: physical = logical ^ ((row&7)<<4))
    const int sel = lane >> 3, l7 = lane & 7;
    const uint32_t xm = (uint32_t)l7 << 4;
    const int mwarp = (wid & 1) * 64;
    const int nwarp = (wid >> 1) * 64;
    const int rA = ((sel & 1) << 3) + l7;            // A: sel0,2 -> rows 0-7; sel1,3 -> rows 8-15
    const uint32_t kbA = (uint32_t)(sel >> 1) << 4;  // A: sel2,3 -> k+8 (16B)
    const int rB = (((sel >> 1) & 1) << 3) + l7;     // B: sel2,3 -> n+8
    const uint32_t kbB = (uint32_t)(sel & 1) << 4;   // B: sel1,3 -> k+8
    uint32_t rowA[4], rowB[4];
    #pragma unroll
    for (int f = 0; f < 4; f++) rowA[f] = (uint32_t)(mwarp + f * 16 + rA) * 128u;
    #pragma unroll
    for (int g = 0; g < 4; g++) rowB[g] = (uint32_t)(nwarp + g * 16 + rB) * 128u + (uint32_t)A_BYTES;

    uint32_t g = 0;                                  // global chunk counter (ring position)
    #pragma unroll 1
    for (int tl = 0; tl < ntiles; tl++) {
        const int t  = bid + tl * gsz;               // lockstep waves: good L2 tile sharing
        const int m0 = (t >> 4) * TILE_M;
        const int n0 = (t & 15) * TILE_N;

        float d[4][8][4] = {};

        #pragma unroll 1
        for (int i = 0; i < NCHUNKS; i++, g++) {
            const uint32_t s  = g & (STAGES - 1);
            const uint32_t ph = (g >> 2) & 1u;
            MBAR_WAIT(sb + OFF_FULL(s), ph);
            const uint32_t st = sb + SMEM_CTRL + s * STAGE_BYTES;

            #pragma unroll
            for (int kk = 0; kk < KCHUNK / 16; kk++) {
                const uint32_t kb = (uint32_t)kk << 5;          // kk*32 bytes
                uint32_t bb[4][4], aa[4][4];
                #pragma unroll
                for (int gg = 0; gg < 4; gg++) ldsm4(bb[gg], st + rowB[gg] + ((kb + kbB) ^ xm));
                #pragma unroll
                for (int f = 0; f < 4; f++) ldsm4(aa[f], st + rowA[f] + ((kb + kbA) ^ xm));
                #pragma unroll
                for (int f = 0; f < 4; f++)
                    #pragma unroll
                    for (int gg = 0; gg < 4; gg++) {
                        mma16816(d[f][2 * gg],     aa[f], &bb[gg][0]);
                        mma16816(d[f][2 * gg + 1], aa[f], &bb[gg][2]);
                    }
            }

            __syncwarp();
            if (lane == 0) MBAR_ARRIVE(sb + OFF_EMPTY(s));

            // producer: refill this slot with chunk g+STAGES (may belong to next tile)
            if (tid == 0 && g + STAGES < totalChunks) {
                MBAR_WAIT(sb + OFF_EMPTY(s), ph);               // completion #(g>>2) on this slot
                const uint32_t f  = g + STAGES;
                const int ftl     = (int)(f >> 6);              // f / NCHUNKS
                const int fch     = (int)(f & 63);
                const int ft      = bid + ftl * gsz;
                const int fm0     = (ft >> 4) * TILE_M;
                const int fn0     = (ft & 15) * TILE_N;
                MBAR_EXPECT_TX(sb + OFF_FULL(s), STAGE_BYTES);
                tma2d(st,           &tm_x, fch * KCHUNK, fm0, sb + OFF_FULL(s));
                tma2d(st + A_BYTES, &tm_w, fch * KCHUNK, fn0, sb + OFF_FULL(s));
            }
        }

        // ---- epilogue: registers -> gmem, add bias (overlaps next tile's TMAs) ----
        const int g2 = lane >> 2, tg = lane & 3;
        float bv0[8], bv1[8];
        #pragma unroll
        for (int nf = 0; nf < 8; nf++) {
            const int n = n0 + nwarp + nf * 8 + tg * 2;
            bv0[nf] = bias[n];
            bv1[nf] = bias[n + 1];
        }
        #pragma unroll
        for (int f = 0; f < 4; f++) {
            const int mrow = m0 + mwarp + f * 16 + g2;
            #pragma unroll
            for (int nf = 0; nf < 8; nf++) {
                const int n = n0 + nwarp + nf * 8 + tg * 2;
                float2 v0 = make_float2(d[f][nf][0] + bv0[nf], d[f][nf][1] + bv1[nf]);
                float2 v1 = make_float2(d[f][nf][2] + bv0[nf], d[f][nf][3] + bv1[nf]);
                *reinterpret_cast<float2*>(&out[(size_t)mrow * N_DIM + n]) = v0;
                *reinterpret_cast<float2*>(&out[(size_t)(mrow + 8) * N_DIM + n]) = v1;
            }
        }
    }
}

// ---------------- host ----------------
typedef CUresult (*PFN_EncodeTiled)(
    CUtensorMap*, CUtensorMapDataType, cuuint32_t, void*,
    const cuuint64_t*, const cuuint64_t*, const cuuint32_t*, const cuuint32_t*,
    CUtensorMapInterleave, CUtensorMapSwizzle, CUtensorMapL2promotion, CUtensorMapFloatOOBfill);

static void make_map_2d(PFN_EncodeTiled fn, CUtensorMap* m, void* ptr,
                        uint64_t rows, uint32_t boxRows) {
    cuuint64_t dims[2]    = {(cuuint64_t)K_DIM, (cuuint64_t)rows};
    cuuint64_t strides[1] = {(cuuint64_t)K_DIM * 2};
    cuuint32_t box[2]     = {(cuuint32_t)KCHUNK, boxRows};   // 64 fp16 = 128B (SW128 limit)
    cuuint32_t es[2]      = {1, 1};
    fn(m, CU_TENSOR_MAP_DATA_TYPE_FLOAT16, 2, ptr, dims, strides, box, es,
       CU_TENSOR_MAP_INTERLEAVE_NONE, CU_TENSOR_MAP_SWIZZLE_128B,
       CU_TENSOR_MAP_L2_PROMOTION_L2_128B, CU_TENSOR_MAP_FLOAT_OOB_FILL_NONE);
}

extern "C" void kernel_launch(void* const* d_in, const int* in_sizes, int n_in,
                              void* d_out, int out_size) {
    const float* x    = (const float*)d_in[0];
    const float* w    = (const float*)d_in[1];
    const float* bias = (const float*)d_in[2];
    float* out = (float*)d_out;

    void *p_wdq, *p_xh;
    cudaGetSymbolAddress(&p_wdq, g_wdq);
    cudaGetSymbolAddress(&p_xh, g_xh);

    // 1) fused: quantize W -> exact fp16 plane, convert x -> fp16
    prep_kernel<<<QUANT_BLOCKS + CONV_BLOCKS, 256>>>(
        (const float4*)w, (uint4*)p_wdq, (const float4*)x, (uint4*)p_xh);

    // 2) tensor maps (host-side; happens at graph-capture time, free at replay)
    PFN_EncodeTiled fn = nullptr;
    cudaDriverEntryPointQueryResult qres;
    cudaGetDriverEntryPointByVersion("cuTensorMapEncodeTiled", (void**)&fn, 12000,
                                     cudaEnableDefault, &qres);
    if (!fn) return;

    CUtensorMap tm_x, tm_w;
    make_map_2d(fn, &tm_x, p_xh,  M_DIM, TILE_M);
    make_map_2d(fn, &tm_w, p_wdq, N_DIM, TILE_N);

    cudaFuncSetAttribute(gemm_kernel, cudaFuncAttributeMaxDynamicSharedMemorySize, SMEM_REQ);
    gemm_kernel<<<GRID_SM, 256, SMEM_REQ>>>(tm_x, tm_w, bias, out);
}